// round 4
// baseline (speedup 1.0000x reference)
#include <cuda_runtime.h>
#include <math.h>

#define B_N    256
#define T_PAST 20
#define T_FUT  30
#define NT     256
#define NBLK   (B_N / 2)

// ---- shared weights (float indices) ----
#define SM_WT1   0        // 4*32*36 = 4608  conv1 [kk][co][ci] stride 36
#define SM_WT2   4608
#define SM_WT3   9216
#define SM_WT0   13824    // 4*32*2
#define SM_CB    14080    // 128
#define SM_DWIH  14208    // 96*36
#define SM_DWHH  17664    // 96*36
#define SM_WC    21120    // 128
#define SM_BC    21248    // 4
#define SM_PB    21252    // per-batch region x2
// per-batch offsets (within PB)
#define PB_A0    0        // 800
#define PB_A1    800      // 512
#define PB_A2    1312     // 288
#define PB_LID   1600     // 72
#define PB_X     1672     // 36 (34 used)
#define PB_H     1708     // 32
#define PB_GI    1740     // 96
#define PB_GH    1836     // 96
#define PB_Y     1932     // 4: y1[0],y1[1],y2[0],y2[1]
#define PB_LD    1936     // 2
#define PB_Q4    1938     // 4: f0,f1,ay,ax
#define PB_SIZE  1952
#define SM_TOTAL (SM_PB + 2 * PB_SIZE)
#define SMEM_BYTES (SM_TOTAL * 4)

typedef unsigned long long ull;

__device__ float g_Wc[128];
__device__ float g_bc[4];

__device__ __forceinline__ void ffma2(ull& d, ull a, ull b) {
    asm("fma.rn.f32x2 %0, %1, %2, %0;" : "+l"(d) : "l"(a), "l"(b));
}
__device__ __forceinline__ float hsum2(ull v) {
    float lo, hi;
    asm("mov.b64 {%0,%1}, %2;" : "=f"(lo), "=f"(hi) : "l"(v));
    return lo + hi;
}
__device__ __forceinline__ float sigmoidf_(float x) {
    return 1.f / (1.f + expf(-x));
}

__global__ void combine_mlp_kernel(const float* __restrict__ w1,
                                   const float* __restrict__ b1,
                                   const float* __restrict__ w2,
                                   const float* __restrict__ b2)
{
    int tid = threadIdx.x;            // 128 threads
    int o = tid >> 5, i = tid & 31;
    const float* w2r = w2 + o * 512;
    float a0 = 0.f, a1 = 0.f, a2 = 0.f, a3 = 0.f;
    #pragma unroll 4
    for (int k = 0; k < 512; k += 4) {
        a0 = fmaf(w2r[k + 0], w1[(k + 0) * 32 + i], a0);
        a1 = fmaf(w2r[k + 1], w1[(k + 1) * 32 + i], a1);
        a2 = fmaf(w2r[k + 2], w1[(k + 2) * 32 + i], a2);
        a3 = fmaf(w2r[k + 3], w1[(k + 3) * 32 + i], a3);
    }
    g_Wc[tid] = (a0 + a1) + (a2 + a3);
    if (tid < 4) {
        float acc = b2[tid];
        for (int k = 0; k < 512; ++k) acc = fmaf(w2[tid * 512 + k], b1[k], acc);
        g_bc[tid] = acc;
    }
}

// One conv tile: CPW cells starting at cb, lane = output channel.
template <int OS, int IS, int CPW>
__device__ __forceinline__ void conv_tile(const float* __restrict__ ain,
                                          float* __restrict__ aout,
                                          const float* __restrict__ wT,
                                          const float* __restrict__ bias,
                                          int cb, int fy, int fx, int lane)
{
    int rr[CPW], xx[CPW];
    #pragma unroll
    for (int c = 0; c < CPW; ++c) { rr[c] = (cb + c) / OS; xx[c] = (cb + c) % OS; }

    ull acc[CPW][2];
    #pragma unroll
    for (int c = 0; c < CPW; ++c) { acc[c][0] = 0ULL; acc[c][1] = 0ULL; }

    #pragma unroll
    for (int kk = 0; kk < 4; ++kk) {
        const int kh = kk >> 1, kw = kk & 1;
        const ulonglong2* wp = (const ulonglong2*)(wT + (kk * 32 + lane) * 36);
        const ulonglong2* ap[CPW];
        #pragma unroll
        for (int c = 0; c < CPW; ++c)
            ap[c] = (const ulonglong2*)(ain + ((rr[c] + kh) * IS + (xx[c] + kw)) * 32);
        #pragma unroll
        for (int q = 0; q < 8; ++q) {
            ulonglong2 wv = wp[q];
            #pragma unroll
            for (int c = 0; c < CPW; ++c) {
                ulonglong2 av = ap[c][q];
                ffma2(acc[c][0], av.x, wv.x);
                ffma2(acc[c][1], av.y, wv.y);
            }
        }
    }
    const float bl = bias[lane];
    #pragma unroll
    for (int c = 0; c < CPW; ++c) {
        float o = hsum2(acc[c][0]) + hsum2(acc[c][1]) + bl;
        o = fmaxf(o, 0.f);
        if (fy + rr[c] > 99 || fx + xx[c] > 99) o = 0.f;
        aout[(cb + c) * 32 + lane] = o;
    }
}

extern __shared__ float sm[];

__global__ void __launch_bounds__(NT)
r2p2_kernel(const float* __restrict__ z,
            const float* __restrict__ pp,
            const float* __restrict__ lidar,
            const float* __restrict__ c0w, const float* __restrict__ c0b,
            const float* __restrict__ c1w, const float* __restrict__ c1b,
            const float* __restrict__ c2w, const float* __restrict__ c2b,
            const float* __restrict__ c3w, const float* __restrict__ c3b,
            const float* __restrict__ ewih, const float* __restrict__ ewhh,
            const float* __restrict__ ebih, const float* __restrict__ ebhh,
            const float* __restrict__ dwih, const float* __restrict__ dwhh,
            const float* __restrict__ dbih, const float* __restrict__ dbhh,
            float* __restrict__ out)
{
    const int tid  = threadIdx.x;
    const int half = tid >> 7;          // which batch of the pair
    const int lt   = tid & 127;         // local tid within half
    const int b    = blockIdx.x * 2 + half;

    float* WT1 = sm + SM_WT1;  float* WT2 = sm + SM_WT2;  float* WT3 = sm + SM_WT3;
    float* WT0 = sm + SM_WT0;  float* CB  = sm + SM_CB;
    float* DWIH = sm + SM_DWIH; float* DWHH = sm + SM_DWHH;
    float* WC = sm + SM_WC;    float* BC = sm + SM_BC;
    float* PB  = sm + SM_PB + half * PB_SIZE;   // this thread's batch region
    float* A0h = PB + PB_A0;  float* A1h = PB + PB_A1;  float* A2h = PB + PB_A2;
    float* LIDh = PB + PB_LID; float* Xh = PB + PB_X;   float* Hh = PB + PB_H;
    float* GIh = PB + PB_GI;   float* GHh = PB + PB_GH;
    float* Yh  = PB + PB_Y;    float* LDh = PB + PB_LD; float* Q4h = PB + PB_Q4;

    // ---- load + transpose conv weights: HWIO (kk,ci,co) -> [kk][co][ci] ----
    {
        const float* srcs[3] = { c1w, c2w, c3w };
        float* dsts[3] = { WT1, WT2, WT3 };
        #pragma unroll
        for (int l = 0; l < 3; ++l) {
            const float* s = srcs[l]; float* d = dsts[l];
            for (int idx = tid; idx < 4096; idx += NT) {
                int co = idx & 31, ci = (idx >> 5) & 31, kk = idx >> 10;
                d[(kk * 32 + co) * 36 + ci] = s[idx];
            }
        }
        for (int idx = tid; idx < 256; idx += NT) {
            int co = idx & 31, ci = (idx >> 5) & 1, kk = idx >> 6;
            WT0[(kk * 32 + co) * 2 + ci] = c0w[idx];
        }
    }
    if (tid < 32) {
        CB[tid] = c0b[tid]; CB[32 + tid] = c1b[tid];
        CB[64 + tid] = c2b[tid]; CB[96 + tid] = c3b[tid];
    }
    for (int idx = tid; idx < 96 * 34; idx += NT) {
        int j = idx / 34, k = idx % 34;
        DWIH[j * 36 + k] = dwih[idx];
    }
    for (int idx = tid; idx < 96 * 32; idx += NT) {
        int j = idx >> 5, k = idx & 31;
        DWHH[j * 36 + k] = dwhh[idx];
    }
    if (tid < 128) WC[tid] = g_Wc[tid];
    if (tid < 4)   BC[tid] = g_bc[tid];
    if (lt < 32)   Hh[lt] = 0.f;
    if (lt < 2) {
        Yh[lt]     = pp[(b * T_PAST + 19) * 2 + lt];   // y_{t-1}
        Yh[2 + lt] = pp[(b * T_PAST + 18) * 2 + lt];   // y_{t-2}
    }
    __syncthreads();

    // ---- encoder GRU: 20 steps, both batches in parallel ----
    for (int t = 0; t < T_PAST; ++t) {
        if (lt < 96) {
            float x0 = pp[(b * T_PAST + t) * 2];
            float x1 = pp[(b * T_PAST + t) * 2 + 1];
            float gi = ebih[lt] + x0 * ewih[lt * 2] + x1 * ewih[lt * 2 + 1];
            ull g0 = 0ULL, g1 = 0ULL;
            const float4* wr = (const float4*)(ewhh + lt * 32);
            const ulonglong2* hp = (const ulonglong2*)Hh;
            #pragma unroll
            for (int k = 0; k < 8; ++k) {
                float4 wf = wr[k];
                ulonglong2 wv = *(const ulonglong2*)&wf;
                ulonglong2 hv = hp[k];
                ffma2(g0, hv.x, wv.x);
                ffma2(g1, hv.y, wv.y);
            }
            GIh[lt] = gi;
            GHh[lt] = ebhh[lt] + hsum2(g0) + hsum2(g1);
        }
        __syncthreads();
        if (lt < 32) {
            float r  = sigmoidf_(GIh[lt] + GHh[lt]);
            float zg = sigmoidf_(GIh[32 + lt] + GHh[32 + lt]);
            float n  = tanhf(GIh[64 + lt] + r * GHh[64 + lt]);
            Hh[lt] = (1.f - zg) * n + zg * Hh[lt];
        }
        __syncthreads();
    }

    // ---- decoder: 30 autoregressive steps ----
    float logdet = 0.f;   // live in threads with lt<2 of each half
    for (int t = 0; t < T_FUT; ++t) {
        // Phase A: GH matvec (lt<96) concurrently with lidar patch load (lt>=96)
        if (lt < 96) {
            ull g0 = 0ULL, g1 = 0ULL;
            const ulonglong2* hr = (const ulonglong2*)(DWHH + lt * 36);
            const ulonglong2* hp = (const ulonglong2*)Hh;
            #pragma unroll
            for (int k = 0; k < 8; ++k) {
                ulonglong2 wv = hr[k];
                ulonglong2 hv = hp[k];
                ffma2(g0, hv.x, wv.x);
                ffma2(g1, hv.y, wv.y);
            }
            GHh[lt] = dbhh[lt] + hsum2(g0) + hsum2(g1);
        } else {
            float q0c = Yh[0], q1c = Yh[1];
            float f0 = fminf(fmaxf(floorf(q0c), 0.f), 98.f);
            float f1 = fminf(fmaxf(floorf(q1c), 0.f), 98.f);
            int fy = (int)f0, fx = (int)f1;
            if (lt == 96) {
                Q4h[0] = f0; Q4h[1] = f1;
                Q4h[2] = fminf(fmaxf(q0c - f0, 0.f), 1.f);   // ay
                Q4h[3] = fminf(fmaxf(q1c - f1, 0.f), 1.f);   // ax
            }
            int l = lt - 96;                 // 0..31
            #pragma unroll
            for (int j = 0; j < 3; ++j) {
                int e = l + 32 * j;
                if (e < 72) {
                    int rr = e / 12, cc = (e % 12) >> 1, ci = e & 1;
                    int gy = fy + rr, gx = fx + cc;
                    float v = 0.f;
                    if (gy < 100 && gx < 100)
                        v = lidar[((b * 100 + gy) * 100 + gx) * 2 + ci];
                    LIDh[e] = v;
                }
            }
        }
        __syncthreads();

        // Phase B: layer0 — 2 batches x 800 outputs over all 256 threads
        for (int idx = tid; idx < 1600; idx += NT) {
            int h2 = idx >= 800;
            int rem = idx - h2 * 800;
            int co = rem & 31, cell = rem >> 5;
            int r = cell / 5, c = cell % 5;
            float* PBo = sm + SM_PB + h2 * PB_SIZE;
            const float* LIDo = PBo + PB_LID;
            int fy = (int)PBo[PB_Q4], fx = (int)PBo[PB_Q4 + 1];
            ull acc = 0ULL;
            #pragma unroll
            for (int kk = 0; kk < 4; ++kk) {
                int kh = kk >> 1, kw = kk & 1;
                ull lv = *(const ull*)(LIDo + ((r + kh) * 6 + (c + kw)) * 2);
                ull wv = *(const ull*)(WT0 + (kk * 32 + co) * 2);
                ffma2(acc, lv, wv);
            }
            float o = fmaxf(hsum2(acc) + CB[co], 0.f);
            if (fy + r > 99 || fx + c > 99) o = 0.f;
            PBo[PB_A0 + cell * 32 + co] = o;
        }
        __syncthreads();

        const int wid  = tid >> 5;
        const int lane = tid & 31;

        // Phase C: layer1 (5->4), 8 warps: batch = wid&1, group = wid>>1, 4 cells
        {
            int h2 = wid & 1, grp = wid >> 1;
            float* PBo = sm + SM_PB + h2 * PB_SIZE;
            int fy = (int)PBo[PB_Q4], fx = (int)PBo[PB_Q4 + 1];
            conv_tile<4, 5, 4>(PBo + PB_A0, PBo + PB_A1, WT1, CB + 32,
                               grp * 4, fy, fx, lane);
        }
        __syncthreads();

        // Phase D: layer2 (4->3), 6 warps: batch = wid&1, group = wid>>1, 3 cells
        if (wid < 6) {
            int h2 = wid & 1, grp = wid >> 1;
            float* PBo = sm + SM_PB + h2 * PB_SIZE;
            int fy = (int)PBo[PB_Q4], fx = (int)PBo[PB_Q4 + 1];
            conv_tile<3, 4, 3>(PBo + PB_A1, PBo + PB_A2, WT2, CB + 64,
                               grp * 3, fy, fx, lane);
        }
        __syncthreads();

        // Phase E: layer3 (3->2) all 4 cells in one warp per batch + fused bilinear
        if (wid < 2) {
            int h2 = wid;
            float* PBo = sm + SM_PB + h2 * PB_SIZE;
            const float* ain = PBo + PB_A2;
            int fy = (int)PBo[PB_Q4], fx = (int)PBo[PB_Q4 + 1];
            float ay = PBo[PB_Q4 + 2], ax = PBo[PB_Q4 + 3];

            ull acc[4][2];
            #pragma unroll
            for (int c = 0; c < 4; ++c) { acc[c][0] = 0ULL; acc[c][1] = 0ULL; }
            #pragma unroll
            for (int kk = 0; kk < 4; ++kk) {
                const int kh = kk >> 1, kw = kk & 1;
                const ulonglong2* wp = (const ulonglong2*)(WT3 + (kk * 32 + lane) * 36);
                #pragma unroll
                for (int q = 0; q < 8; ++q) {
                    ulonglong2 wv = wp[q];
                    #pragma unroll
                    for (int c = 0; c < 4; ++c) {
                        int r = c >> 1, x = c & 1;
                        const ulonglong2* ap =
                            (const ulonglong2*)(ain + ((r + kh) * 3 + (x + kw)) * 32);
                        ulonglong2 av = ap[q];
                        ffma2(acc[c][0], av.x, wv.x);
                        ffma2(acc[c][1], av.y, wv.y);
                    }
                }
            }
            const float bl = CB[96 + lane];
            float o[4];
            #pragma unroll
            for (int c = 0; c < 4; ++c) {
                int r = c >> 1, x = c & 1;
                float v = hsum2(acc[c][0]) + hsum2(acc[c][1]) + bl;
                v = fmaxf(v, 0.f);
                if (fy + r > 99 || fx + x > 99) v = 0.f;
                o[c] = v;
            }
            float top = o[0] + ax * (o[1] - o[0]);
            float bot = o[2] + ax * (o[3] - o[2]);
            PBo[PB_X + 2 + lane] = top + ay * (bot - top);
            if (lane < 2) PBo[PB_X + lane] = PBo[PB_Y + lane];
        }
        __syncthreads();

        // Phase F: GI matvec (input gates), 96 threads per half
        if (lt < 96) {
            ull a0 = 0ULL, a1 = 0ULL;
            const ulonglong2* wr = (const ulonglong2*)(DWIH + lt * 36);
            const ulonglong2* xp = (const ulonglong2*)Xh;
            #pragma unroll
            for (int k = 0; k < 8; ++k) {
                ulonglong2 wv = wr[k];
                ulonglong2 xv = xp[k];
                ffma2(a0, xv.x, wv.x);
                ffma2(a1, xv.y, wv.y);
            }
            ull wl = *(const ull*)(DWIH + lt * 36 + 32);
            ull xl = *(const ull*)(Xh + 32);
            ffma2(a0, xl, wl);
            GIh[lt] = dbih[lt] + hsum2(a0) + hsum2(a1);
        }
        __syncthreads();

        // Phase G: hidden update + head + y-update (warp 0 of each half)
        if (lt < 32) {
            float r  = sigmoidf_(GIh[lt] + GHh[lt]);
            float zg = sigmoidf_(GIh[32 + lt] + GHh[32 + lt]);
            float n  = tanhf(GIh[64 + lt] + r * GHh[64 + lt]);
            Hh[lt] = (1.f - zg) * n + zg * Hh[lt];
            __syncwarp();
            if (lt < 2) {
                const ulonglong2* hp = (const ulonglong2*)Hh;
                const ulonglong2* w0 = (const ulonglong2*)(WC + lt * 32);
                const ulonglong2* w1 = (const ulonglong2*)(WC + (lt + 2) * 32);
                ull l0 = 0ULL, l1 = 0ULL, s0 = 0ULL, s1 = 0ULL;
                #pragma unroll
                for (int k = 0; k < 8; ++k) {
                    ulonglong2 hv = hp[k];
                    ulonglong2 wa = w0[k];
                    ulonglong2 wb = w1[k];
                    ffma2(l0, hv.x, wa.x); ffma2(l1, hv.y, wa.y);
                    ffma2(s0, hv.x, wb.x); ffma2(s1, hv.y, wb.y);
                }
                float loc = BC[lt] + hsum2(l0) + hsum2(l1);
                float sp  = BC[lt + 2] + hsum2(s0) + hsum2(s1);
                float s   = (sp > 20.f) ? sp : log1pf(expf(sp));
                float zt  = z[(b * T_FUT + t) * 2 + lt];
                float yn  = 2.f * Yh[lt] - Yh[2 + lt] + loc + s * zt;
                out[(b * T_FUT + t) * 2 + lt] = yn;
                logdet += logf(s);
                Yh[2 + lt] = Yh[lt];
                Yh[lt] = yn;
            }
        }
        __syncthreads();   // Y/H/GH consistency for next step
    }

    if (lt < 2) LDh[lt] = logdet;
    __syncthreads();
    if (lt == 0) out[B_N * T_FUT * 2 + b] = LDh[0] + LDh[1];
}

extern "C" void kernel_launch(void* const* d_in, const int* in_sizes, int n_in,
                              void* d_out, int out_size)
{
    const float* z    = (const float*)d_in[0];
    const float* pp   = (const float*)d_in[1];
    const float* lid  = (const float*)d_in[2];
    const float* c0w  = (const float*)d_in[3];
    const float* c0b  = (const float*)d_in[4];
    const float* c1w  = (const float*)d_in[5];
    const float* c1b  = (const float*)d_in[6];
    const float* c2w  = (const float*)d_in[7];
    const float* c2b  = (const float*)d_in[8];
    const float* c3w  = (const float*)d_in[9];
    const float* c3b  = (const float*)d_in[10];
    const float* ewih = (const float*)d_in[11];
    const float* ewhh = (const float*)d_in[12];
    const float* ebih = (const float*)d_in[13];
    const float* ebhh = (const float*)d_in[14];
    const float* dwih = (const float*)d_in[15];
    const float* dwhh = (const float*)d_in[16];
    const float* dbih = (const float*)d_in[17];
    const float* dbhh = (const float*)d_in[18];
    const float* w1   = (const float*)d_in[19];
    const float* b1   = (const float*)d_in[20];
    const float* w2   = (const float*)d_in[21];
    const float* b2   = (const float*)d_in[22];
    float* out = (float*)d_out;

    cudaFuncSetAttribute(r2p2_kernel,
                         cudaFuncAttributeMaxDynamicSharedMemorySize, SMEM_BYTES);

    combine_mlp_kernel<<<1, 128>>>(w1, b1, w2, b2);
    r2p2_kernel<<<NBLK, NT, SMEM_BYTES>>>(z, pp, lid,
        c0w, c0b, c1w, c1b, c2w, c2b, c3w, c3b,
        ewih, ewhh, ebih, ebhh, dwih, dwhh, dbih, dbhh, out);
}

// round 5
// speedup vs baseline: 1.0661x; 1.0661x over previous
#include <cuda_runtime.h>
#include <math.h>

#define B_N    256
#define T_PAST 20
#define T_FUT  30
#define NT     128

typedef unsigned long long ull;

// ---- pre-transposed weight buffers (device globals; filled by prep kernels) ----
__device__ float g_WTc[12288];   // conv1..3: [(l*4+kk)*8+q][co][4]  (ci = 4q+i)
__device__ float g_WT0p[256];    // conv0: [kk][co][ci(2)]
__device__ float g_EWHHt[3072];  // enc whh: [k4][j][4]
__device__ float g_DWIHt[3456];  // dec wih: [k4(9)][j][4], zero-padded k=34,35
__device__ float g_DWHHt[3072];  // dec whh: [k4][j][4]
__device__ float g_Wc[128];      // collapsed MLP 4x32
__device__ float g_bc[4];

__device__ __forceinline__ void ffma2(ull& d, ull a, ull b) {
    asm("fma.rn.f32x2 %0, %1, %2, %0;" : "+l"(d) : "l"(a), "l"(b));
}
__device__ __forceinline__ float hsum2(ull v) {
    float lo, hi;
    asm("mov.b64 {%0,%1}, %2;" : "=f"(lo), "=f"(hi) : "l"(v));
    return lo + hi;
}
__device__ __forceinline__ float sigmoidf_(float x) {
    return 1.f / (1.f + expf(-x));
}

// Collapse the linear MLP: Wc = W2 @ W1 (4x32), bc = W2 @ b1 + b2 (4)
__global__ void combine_mlp_kernel(const float* __restrict__ w1,
                                   const float* __restrict__ b1,
                                   const float* __restrict__ w2,
                                   const float* __restrict__ b2)
{
    int tid = threadIdx.x;            // 128 threads
    int o = tid >> 5, i = tid & 31;
    const float* w2r = w2 + o * 512;
    float a0 = 0.f, a1 = 0.f, a2 = 0.f, a3 = 0.f;
    #pragma unroll 4
    for (int k = 0; k < 512; k += 4) {
        a0 = fmaf(w2r[k + 0], w1[(k + 0) * 32 + i], a0);
        a1 = fmaf(w2r[k + 1], w1[(k + 1) * 32 + i], a1);
        a2 = fmaf(w2r[k + 2], w1[(k + 2) * 32 + i], a2);
        a3 = fmaf(w2r[k + 3], w1[(k + 3) * 32 + i], a3);
    }
    g_Wc[tid] = (a0 + a1) + (a2 + a3);
    if (tid < 4) {
        float acc = b2[tid];
        for (int k = 0; k < 512; ++k) acc = fmaf(w2[tid * 512 + k], b1[k], acc);
        g_bc[tid] = acc;
    }
}

// Transpose all weights into coalesced-read layouts.
__global__ void prep_transpose(const float* __restrict__ c0w,
                               const float* __restrict__ c1w,
                               const float* __restrict__ c2w,
                               const float* __restrict__ c3w,
                               const float* __restrict__ ewhh,
                               const float* __restrict__ dwih,
                               const float* __restrict__ dwhh)
{
    int idx = blockIdx.x * blockDim.x + threadIdx.x;
    if (idx < 12288) {
        int l = idx >> 12, r = idx & 4095;
        int kk = r >> 10, ci = (r >> 5) & 31, co = r & 31;
        const float* src = (l == 0) ? c1w : (l == 1) ? c2w : c3w;
        g_WTc[((l * 4 + kk) * 8 + (ci >> 2)) * 128 + co * 4 + (ci & 3)] = src[r];
    } else if (idx < 12544) {
        int r = idx - 12288;
        int kk = r >> 6, ci = (r >> 5) & 1, co = r & 31;
        g_WT0p[(kk * 32 + co) * 2 + ci] = c0w[r];
    } else if (idx < 15616) {
        int r = idx - 12544; int j = r >> 5, k = r & 31;
        g_EWHHt[(k >> 2) * 384 + j * 4 + (k & 3)] = ewhh[r];
    } else if (idx < 19072) {
        int r = idx - 15616; int j = r / 34, k = r % 34;
        g_DWIHt[(k >> 2) * 384 + j * 4 + (k & 3)] = dwih[r];
    } else if (idx < 19264) {
        int r = idx - 19072; int j = r >> 1, i = r & 1;
        g_DWIHt[8 * 384 + j * 4 + 2 + i] = 0.f;    // pad k=34,35
    } else if (idx < 22336) {
        int r = idx - 19264; int j = r >> 5, k = r & 31;
        g_DWHHt[(k >> 2) * 384 + j * 4 + (k & 3)] = dwhh[r];
    }
}

// Conv tile: CPW cells starting at cb, lane = output channel.
// Activations from smem (warp-broadcast); weights via coalesced LDG.128.
template <int OS, int IS, int CPW>
__device__ __forceinline__ void conv_tile_g(const float* __restrict__ ain,
                                            float* __restrict__ aout,
                                            int lsel,
                                            const float* __restrict__ bias,
                                            int cb, int fy, int fx, int lane)
{
    int rr[CPW], xx[CPW];
    #pragma unroll
    for (int c = 0; c < CPW; ++c) { rr[c] = (cb + c) / OS; xx[c] = (cb + c) % OS; }

    ull acc[CPW][2];
    #pragma unroll
    for (int c = 0; c < CPW; ++c) { acc[c][0] = 0ULL; acc[c][1] = 0ULL; }

    const ulonglong2* __restrict__ wb =
        (const ulonglong2*)g_WTc + (lsel * 4) * 8 * 32;

    #pragma unroll
    for (int kk = 0; kk < 4; ++kk) {
        const int kh = kk >> 1, kw = kk & 1;
        const ulonglong2* ap[CPW];
        #pragma unroll
        for (int c = 0; c < CPW; ++c)
            ap[c] = (const ulonglong2*)(ain + ((rr[c] + kh) * IS + (xx[c] + kw)) * 32);
        #pragma unroll
        for (int q = 0; q < 8; ++q) {
            ulonglong2 wv = __ldg(&wb[(kk * 8 + q) * 32 + lane]);  // coalesced 512B/warp
            #pragma unroll
            for (int c = 0; c < CPW; ++c) {
                ulonglong2 av = ap[c][q];                          // smem broadcast
                ffma2(acc[c][0], av.x, wv.x);
                ffma2(acc[c][1], av.y, wv.y);
            }
        }
    }
    const float bl = __ldg(bias + lane);
    #pragma unroll
    for (int c = 0; c < CPW; ++c) {
        float o = hsum2(acc[c][0]) + hsum2(acc[c][1]) + bl;
        o = fmaxf(o, 0.f);
        if (fy + rr[c] > 99 || fx + xx[c] > 99) o = 0.f;
        aout[(cb + c) * 32 + lane] = o;
    }
}

__global__ void __launch_bounds__(NT, 4)
r2p2_kernel(const float* __restrict__ z,
            const float* __restrict__ pp,
            const float* __restrict__ lidar,
            const float* __restrict__ c0b, const float* __restrict__ c1b,
            const float* __restrict__ c2b, const float* __restrict__ c3b,
            const float* __restrict__ ewih,
            const float* __restrict__ ebih, const float* __restrict__ ebhh,
            const float* __restrict__ dbih, const float* __restrict__ dbhh,
            float* __restrict__ out)
{
    const int b = blockIdx.x;
    const int tid = threadIdx.x;
    const int wid = tid >> 5, lane = tid & 31;

    __shared__ float A0[800], A1[512], A2[288];
    __shared__ float LID[72], X[36], H[32], GI[96], GH[96];
    __shared__ float Y[4], Q4[4], LD[2];

    if (tid < 32) H[tid] = 0.f;
    if (tid == 34 || tid == 35) X[tid] = 0.f;   // padding (k=34,35 weights are 0)
    if (tid < 2) {
        Y[tid]     = pp[(b * T_PAST + 19) * 2 + tid];   // y_{t-1}
        Y[2 + tid] = pp[(b * T_PAST + 18) * 2 + tid];   // y_{t-2}
    }
    __syncthreads();

    // ---- encoder GRU: 20 steps ----
    for (int t = 0; t < T_PAST; ++t) {
        if (tid < 96) {
            float x0 = __ldg(pp + (b * T_PAST + t) * 2);
            float x1 = __ldg(pp + (b * T_PAST + t) * 2 + 1);
            float gi = __ldg(ebih + tid) + x0 * __ldg(ewih + tid * 2)
                                         + x1 * __ldg(ewih + tid * 2 + 1);
            ull g0 = 0ULL, g1 = 0ULL;
            const ulonglong2* __restrict__ wp = (const ulonglong2*)g_EWHHt;
            const ulonglong2* hp = (const ulonglong2*)H;
            #pragma unroll
            for (int k4 = 0; k4 < 8; ++k4) {
                ulonglong2 wv = __ldg(&wp[k4 * 96 + tid]);
                ulonglong2 hv = hp[k4];
                ffma2(g0, hv.x, wv.x);
                ffma2(g1, hv.y, wv.y);
            }
            GI[tid] = gi;
            GH[tid] = __ldg(ebhh + tid) + hsum2(g0) + hsum2(g1);
        }
        __syncthreads();
        if (tid < 32) {
            float r  = sigmoidf_(GI[tid] + GH[tid]);
            float zg = sigmoidf_(GI[32 + tid] + GH[32 + tid]);
            float n  = tanhf(GI[64 + tid] + r * GH[64 + tid]);
            H[tid] = (1.f - zg) * n + zg * H[tid];
        }
        __syncthreads();
    }

    // ---- decoder: 30 autoregressive steps ----
    float logdet = 0.f;   // live in tid 0,1
    for (int t = 0; t < T_FUT; ++t) {
        // Phase A: GH matvec (tid<96) || lidar patch + coords (tid>=96)
        if (tid < 96) {
            ull g0 = 0ULL, g1 = 0ULL;
            const ulonglong2* __restrict__ wp = (const ulonglong2*)g_DWHHt;
            const ulonglong2* hp = (const ulonglong2*)H;
            #pragma unroll
            for (int k4 = 0; k4 < 8; ++k4) {
                ulonglong2 wv = __ldg(&wp[k4 * 96 + tid]);
                ulonglong2 hv = hp[k4];
                ffma2(g0, hv.x, wv.x);
                ffma2(g1, hv.y, wv.y);
            }
            GH[tid] = __ldg(dbhh + tid) + hsum2(g0) + hsum2(g1);
        } else {
            float q0c = Y[0], q1c = Y[1];
            float f0 = fminf(fmaxf(floorf(q0c), 0.f), 98.f);
            float f1 = fminf(fmaxf(floorf(q1c), 0.f), 98.f);
            int fy = (int)f0, fx = (int)f1;
            if (tid == 96) {
                Q4[0] = f0; Q4[1] = f1;
                Q4[2] = fminf(fmaxf(q0c - f0, 0.f), 1.f);   // ay
                Q4[3] = fminf(fmaxf(q1c - f1, 0.f), 1.f);   // ax
            }
            int l = tid - 96;                // 0..31
            #pragma unroll
            for (int j = 0; j < 3; ++j) {
                int e = l + 32 * j;
                if (e < 72) {
                    int rr = e / 12, cc = (e % 12) >> 1, ci = e & 1;
                    int gy = fy + rr, gx = fx + cc;
                    float v = 0.f;
                    if (gy < 100 && gx < 100)
                        v = lidar[((b * 100 + gy) * 100 + gx) * 2 + ci];
                    LID[e] = v;
                }
            }
        }
        __syncthreads();

        const int fy = (int)Q4[0], fx = (int)Q4[1];

        // Phase B: layer0 — 800 outputs over 128 threads
        #pragma unroll
        for (int it = 0; it < 7; ++it) {
            int idx = tid + it * NT;
            if (idx < 800) {
                int co = idx & 31, cell = idx >> 5;
                int r = cell / 5, c = cell % 5;
                ull acc = 0ULL;
                #pragma unroll
                for (int kk = 0; kk < 4; ++kk) {
                    int kh = kk >> 1, kw = kk & 1;
                    ull lv = *(const ull*)(LID + ((r + kh) * 6 + (c + kw)) * 2);
                    ull wv = __ldg((const ull*)(g_WT0p + (kk * 32 + co) * 2));
                    ffma2(acc, lv, wv);
                }
                float o = fmaxf(hsum2(acc) + __ldg(c0b + co), 0.f);
                if (fy + r > 99 || fx + c > 99) o = 0.f;
                A0[cell * 32 + co] = o;
            }
        }
        __syncthreads();

        // Phase C: layer1 (5->4), 4 warps x 4 cells
        conv_tile_g<4, 5, 4>(A0, A1, 0, c1b, wid * 4, fy, fx, lane);
        __syncthreads();

        // Phase D: layer2 (4->3), 3 warps x 3 cells
        if (wid < 3)
            conv_tile_g<3, 4, 3>(A1, A2, 1, c2b, wid * 3, fy, fx, lane);
        __syncthreads();

        // Phase E: layer3 (3->2), warp 0 does all 4 cells + fused bilinear
        if (wid == 0) {
            float ay = Q4[2], ax = Q4[3];
            ull acc[4][2];
            #pragma unroll
            for (int c = 0; c < 4; ++c) { acc[c][0] = 0ULL; acc[c][1] = 0ULL; }
            const ulonglong2* __restrict__ wb =
                (const ulonglong2*)g_WTc + (2 * 4) * 8 * 32;
            #pragma unroll
            for (int kk = 0; kk < 4; ++kk) {
                const int kh = kk >> 1, kw = kk & 1;
                #pragma unroll
                for (int q = 0; q < 8; ++q) {
                    ulonglong2 wv = __ldg(&wb[(kk * 8 + q) * 32 + lane]);
                    #pragma unroll
                    for (int c = 0; c < 4; ++c) {
                        int r = c >> 1, x = c & 1;
                        const ulonglong2* ap =
                            (const ulonglong2*)(A2 + ((r + kh) * 3 + (x + kw)) * 32);
                        ulonglong2 av = ap[q];
                        ffma2(acc[c][0], av.x, wv.x);
                        ffma2(acc[c][1], av.y, wv.y);
                    }
                }
            }
            const float bl = __ldg(c3b + lane);
            float o[4];
            #pragma unroll
            for (int c = 0; c < 4; ++c) {
                int r = c >> 1, x = c & 1;
                float v = hsum2(acc[c][0]) + hsum2(acc[c][1]) + bl;
                v = fmaxf(v, 0.f);
                if (fy + r > 99 || fx + x > 99) v = 0.f;
                o[c] = v;
            }
            float top = o[0] + ax * (o[1] - o[0]);
            float bot = o[2] + ax * (o[3] - o[2]);
            X[2 + lane] = top + ay * (bot - top);
            if (lane < 2) X[lane] = Y[lane];
        }
        __syncthreads();

        // Phase F: GI matvec (96 threads), k runs to 36 (padded)
        if (tid < 96) {
            ull a0 = 0ULL, a1 = 0ULL;
            const ulonglong2* __restrict__ wp = (const ulonglong2*)g_DWIHt;
            const ulonglong2* xp = (const ulonglong2*)X;
            #pragma unroll
            for (int k4 = 0; k4 < 9; ++k4) {
                ulonglong2 wv = __ldg(&wp[k4 * 96 + tid]);
                ulonglong2 xv = xp[k4];
                ffma2(a0, xv.x, wv.x);
                ffma2(a1, xv.y, wv.y);
            }
            GI[tid] = __ldg(dbih + tid) + hsum2(a0) + hsum2(a1);
        }
        __syncthreads();

        // Phase G: hidden update + head + y-update (warp 0)
        if (tid < 32) {
            float r  = sigmoidf_(GI[tid] + GH[tid]);
            float zg = sigmoidf_(GI[32 + tid] + GH[32 + tid]);
            float n  = tanhf(GI[64 + tid] + r * GH[64 + tid]);
            H[tid] = (1.f - zg) * n + zg * H[tid];
            __syncwarp();
            if (tid < 2) {
                const ulonglong2* hp = (const ulonglong2*)H;
                const ulonglong2* w0 = (const ulonglong2*)(g_Wc + tid * 32);
                const ulonglong2* w1 = (const ulonglong2*)(g_Wc + (tid + 2) * 32);
                ull l0 = 0ULL, l1 = 0ULL, s0 = 0ULL, s1 = 0ULL;
                #pragma unroll
                for (int k = 0; k < 8; ++k) {
                    ulonglong2 hv = hp[k];
                    ulonglong2 wa = __ldg(&w0[k]);
                    ulonglong2 wb2 = __ldg(&w1[k]);
                    ffma2(l0, hv.x, wa.x); ffma2(l1, hv.y, wa.y);
                    ffma2(s0, hv.x, wb2.x); ffma2(s1, hv.y, wb2.y);
                }
                float loc = g_bc[tid] + hsum2(l0) + hsum2(l1);
                float sp  = g_bc[tid + 2] + hsum2(s0) + hsum2(s1);
                float s   = (sp > 20.f) ? sp : log1pf(expf(sp));
                float zt  = __ldg(z + (b * T_FUT + t) * 2 + tid);
                float yn  = 2.f * Y[tid] - Y[2 + tid] + loc + s * zt;
                out[(b * T_FUT + t) * 2 + tid] = yn;
                logdet += logf(s);
                Y[2 + tid] = Y[tid];
                Y[tid] = yn;
            }
        }
        __syncthreads();   // Y/H visible for next step
    }

    if (tid < 2) LD[tid] = logdet;
    __syncthreads();
    if (tid == 0) out[B_N * T_FUT * 2 + b] = LD[0] + LD[1];
}

extern "C" void kernel_launch(void* const* d_in, const int* in_sizes, int n_in,
                              void* d_out, int out_size)
{
    const float* z    = (const float*)d_in[0];
    const float* pp   = (const float*)d_in[1];
    const float* lid  = (const float*)d_in[2];
    const float* c0w  = (const float*)d_in[3];
    const float* c0b  = (const float*)d_in[4];
    const float* c1w  = (const float*)d_in[5];
    const float* c1b  = (const float*)d_in[6];
    const float* c2w  = (const float*)d_in[7];
    const float* c2b  = (const float*)d_in[8];
    const float* c3w  = (const float*)d_in[9];
    const float* c3b  = (const float*)d_in[10];
    const float* ewih = (const float*)d_in[11];
    const float* ewhh = (const float*)d_in[12];
    const float* ebih = (const float*)d_in[13];
    const float* ebhh = (const float*)d_in[14];
    const float* dwih = (const float*)d_in[15];
    const float* dwhh = (const float*)d_in[16];
    const float* dbih = (const float*)d_in[17];
    const float* dbhh = (const float*)d_in[18];
    const float* w1   = (const float*)d_in[19];
    const float* b1   = (const float*)d_in[20];
    const float* w2   = (const float*)d_in[21];
    const float* b2   = (const float*)d_in[22];
    float* out = (float*)d_out;

    combine_mlp_kernel<<<1, 128>>>(w1, b1, w2, b2);
    prep_transpose<<<88, 256>>>(c0w, c1w, c2w, c3w, ewhh, dwih, dwhh);
    r2p2_kernel<<<B_N, NT>>>(z, pp, lid,
        c0b, c1b, c2b, c3b, ewih, ebih, ebhh, dbih, dbhh, out);
}

// round 6
// speedup vs baseline: 1.4848x; 1.3928x over previous
#include <cuda_runtime.h>
#include <math.h>

#define B_N    256
#define T_PAST 20
#define T_FUT  30
#define NT     256

// ---- shared memory layout (float indices) ----
#define SM_WT1   0        // 4*32*36 = 4608  conv1 [kk][co][ci] stride 36
#define SM_WT2   4608
#define SM_WT3   9216
#define SM_WT0   13824    // 4*32*2
#define SM_CB    14080    // 128
#define SM_DWIH  14208    // 96*36
#define SM_DWHH  17664    // 96*36
#define SM_WC    21120    // 128
#define SM_BC    21248    // 4
#define SM_A0    21252    // 800
#define SM_A1    22052    // 512
#define SM_A2    22564    // 288
#define SM_A3    22852    // (unused, kept for spacing)
#define SM_LID   22980    // 72
#define SM_X     23052    // 36
#define SM_H     23088    // 32
#define SM_GI    23120    // 96
#define SM_GH    23216    // 96
#define SM_Y     23312    // 4
#define SM_LD    23316    // 2
#define SM_Q4    23320    // 4: f0,f1,ay,ax
#define SM_EWIH  23324    // 96*2
#define SM_EBIH  23516    // 96
#define SM_EBHH  23612    // 96
#define SM_DBIH  23708    // 96
#define SM_DBHH  23804    // 96
#define SM_TOTAL 23900
#define SMEM_BYTES (SM_TOTAL * 4)

typedef unsigned long long ull;

__device__ __forceinline__ void ffma2(ull& d, ull a, ull b) {
    asm("fma.rn.f32x2 %0, %1, %2, %0;" : "+l"(d) : "l"(a), "l"(b));
}
__device__ __forceinline__ float hsum2(ull v) {
    float lo, hi;
    asm("mov.b64 {%0,%1}, %2;" : "=f"(lo), "=f"(hi) : "l"(v));
    return lo + hi;
}
// ---- fast transcendentals (MUFU) ----
__device__ __forceinline__ float fexp2_(float x) {
    float r; asm("ex2.approx.f32 %0, %1;" : "=f"(r) : "f"(x)); return r;
}
__device__ __forceinline__ float flg2_(float x) {
    float r; asm("lg2.approx.f32 %0, %1;" : "=f"(r) : "f"(x)); return r;
}
__device__ __forceinline__ float frcp_(float x) {
    float r; asm("rcp.approx.f32 %0, %1;" : "=f"(r) : "f"(x)); return r;
}
__device__ __forceinline__ float ftanh_(float x) {
    float r; asm("tanh.approx.f32 %0, %1;" : "=f"(r) : "f"(x)); return r;
}
#define LOG2E 1.4426950408889634f
#define LN2   0.6931471805599453f
__device__ __forceinline__ float fsig_(float x) {
    return frcp_(1.f + fexp2_(-LOG2E * x));
}
__device__ __forceinline__ float flogf_(float x) { return flg2_(x) * LN2; }
__device__ __forceinline__ float fsoftplus_(float x) {
    // log1p(exp(x)) ; stable + accurate enough for |x| modest
    return (x > 20.f) ? x : flg2_(1.f + fexp2_(LOG2E * x)) * LN2;
}

// One conv tile: CPW cells starting at cb, lane = output channel.
template <int OS, int IS, int CPW>
__device__ __forceinline__ void conv_tile(const float* __restrict__ ain,
                                          float* __restrict__ aout,
                                          const float* __restrict__ wT,
                                          const float* __restrict__ bias,
                                          int cb, int fy, int fx, int lane)
{
    int rr[CPW], xx[CPW];
    #pragma unroll
    for (int c = 0; c < CPW; ++c) { rr[c] = (cb + c) / OS; xx[c] = (cb + c) % OS; }

    ull acc[CPW][2];
    #pragma unroll
    for (int c = 0; c < CPW; ++c) { acc[c][0] = 0ULL; acc[c][1] = 0ULL; }

    #pragma unroll
    for (int kk = 0; kk < 4; ++kk) {
        const int kh = kk >> 1, kw = kk & 1;
        const ulonglong2* wp = (const ulonglong2*)(wT + (kk * 32 + lane) * 36);
        const ulonglong2* ap[CPW];
        #pragma unroll
        for (int c = 0; c < CPW; ++c)
            ap[c] = (const ulonglong2*)(ain + ((rr[c] + kh) * IS + (xx[c] + kw)) * 32);
        #pragma unroll
        for (int q = 0; q < 8; ++q) {
            ulonglong2 wv = wp[q];
            #pragma unroll
            for (int c = 0; c < CPW; ++c) {
                ulonglong2 av = ap[c][q];
                ffma2(acc[c][0], av.x, wv.x);
                ffma2(acc[c][1], av.y, wv.y);
            }
        }
    }
    const float bl = bias[lane];
    #pragma unroll
    for (int c = 0; c < CPW; ++c) {
        float o = hsum2(acc[c][0]) + hsum2(acc[c][1]) + bl;
        o = fmaxf(o, 0.f);
        if (fy + rr[c] > 99 || fx + xx[c] > 99) o = 0.f;
        aout[(cb + c) * 32 + lane] = o;
    }
}

extern __shared__ float sm[];

__global__ void __launch_bounds__(NT)
r2p2_kernel(const float* __restrict__ z,
            const float* __restrict__ pp,
            const float* __restrict__ lidar,
            const float* __restrict__ c0w, const float* __restrict__ c0b,
            const float* __restrict__ c1w, const float* __restrict__ c1b,
            const float* __restrict__ c2w, const float* __restrict__ c2b,
            const float* __restrict__ c3w, const float* __restrict__ c3b,
            const float* __restrict__ ewih, const float* __restrict__ ewhh,
            const float* __restrict__ ebih, const float* __restrict__ ebhh,
            const float* __restrict__ dwih, const float* __restrict__ dwhh,
            const float* __restrict__ dbih, const float* __restrict__ dbhh,
            const float* __restrict__ w1, const float* __restrict__ b1,
            const float* __restrict__ w2, const float* __restrict__ b2,
            float* __restrict__ out)
{
    const int b = blockIdx.x;
    const int tid = threadIdx.x;
    const int wid = tid >> 5, lane = tid & 31;

    float* WT1 = sm + SM_WT1;  float* WT2 = sm + SM_WT2;  float* WT3 = sm + SM_WT3;
    float* WT0 = sm + SM_WT0;  float* CB  = sm + SM_CB;
    float* DWIH = sm + SM_DWIH; float* DWHH = sm + SM_DWHH;
    float* WC = sm + SM_WC;    float* BC = sm + SM_BC;
    float* A0 = sm + SM_A0;  float* A1 = sm + SM_A1;  float* A2 = sm + SM_A2;
    float* LID = sm + SM_LID; float* X = sm + SM_X;  float* H = sm + SM_H;
    float* GI = sm + SM_GI;   float* GH = sm + SM_GH;
    float* Y  = sm + SM_Y;    float* LD = sm + SM_LD; float* Q4 = sm + SM_Q4;
    float* EWIH = sm + SM_EWIH; float* EBIH = sm + SM_EBIH; float* EBHH = sm + SM_EBHH;
    float* DBIH = sm + SM_DBIH; float* DBHH = sm + SM_DBHH;

    // ---- setup: weight transposes + fused MLP collapse ----
    {
        const float* srcs[3] = { c1w, c2w, c3w };
        float* dsts[3] = { WT1, WT2, WT3 };
        #pragma unroll
        for (int l = 0; l < 3; ++l) {
            const float* s = srcs[l]; float* d = dsts[l];
            for (int idx = tid; idx < 4096; idx += NT) {
                int co = idx & 31, ci = (idx >> 5) & 31, kk = idx >> 10;
                d[(kk * 32 + co) * 36 + ci] = s[idx];
            }
        }
        for (int idx = tid; idx < 256; idx += NT) {
            int co = idx & 31, ci = (idx >> 5) & 1, kk = idx >> 6;
            WT0[(kk * 32 + co) * 2 + ci] = c0w[idx];
        }
    }
    if (tid < 32) {
        CB[tid] = c0b[tid]; CB[32 + tid] = c1b[tid];
        CB[64 + tid] = c2b[tid]; CB[96 + tid] = c3b[tid];
    }
    for (int idx = tid; idx < 96 * 34; idx += NT) {
        int j = idx / 34, k = idx % 34;
        DWIH[j * 36 + k] = dwih[idx];
    }
    for (int idx = tid; idx < 96 * 32; idx += NT) {
        int j = idx >> 5, k = idx & 31;
        DWHH[j * 36 + k] = dwhh[idx];
    }
    if (tid < 96) {
        EWIH[tid * 2] = ewih[tid * 2]; EWIH[tid * 2 + 1] = ewih[tid * 2 + 1];
        EBIH[tid] = ebih[tid]; EBHH[tid] = ebhh[tid];
        DBIH[tid] = dbih[tid]; DBHH[tid] = dbhh[tid];
    }
    // Wc = W2@W1 (threads 0..127), bc = W2@b1+b2 (threads 128..255)
    if (tid < 128) {
        int o = tid >> 5, i = tid & 31;
        const float* w2r = w2 + o * 512;
        float a0 = 0.f, a1 = 0.f, a2 = 0.f, a3 = 0.f;
        #pragma unroll 4
        for (int k = 0; k < 512; k += 4) {
            a0 = fmaf(w2r[k + 0], w1[(k + 0) * 32 + i], a0);
            a1 = fmaf(w2r[k + 1], w1[(k + 1) * 32 + i], a1);
            a2 = fmaf(w2r[k + 2], w1[(k + 2) * 32 + i], a2);
            a3 = fmaf(w2r[k + 3], w1[(k + 3) * 32 + i], a3);
        }
        WC[tid] = (a0 + a1) + (a2 + a3);
    } else {
        int o = (tid - 128) >> 5, l = tid & 31;
        float acc = 0.f;
        #pragma unroll
        for (int k = l; k < 512; k += 32) acc = fmaf(w2[o * 512 + k], b1[k], acc);
        #pragma unroll
        for (int off = 16; off; off >>= 1)
            acc += __shfl_xor_sync(0xffffffffu, acc, off);
        if (l == 0) BC[o] = acc + b2[o];
    }
    if (tid < 32) H[tid] = 0.f;
    if (tid >= 2 && tid < 4) { /* nothing */ }
    if (tid < 2) {
        Y[tid]     = pp[(b * T_PAST + 19) * 2 + tid];   // y_{t-1}
        Y[2 + tid] = pp[(b * T_PAST + 18) * 2 + tid];   // y_{t-2}
    }
    __syncthreads();

    // ---- encoder GRU: 20 steps ----
    for (int t = 0; t < T_PAST; ++t) {
        if (tid < 96) {
            float x0 = pp[(b * T_PAST + t) * 2];
            float x1 = pp[(b * T_PAST + t) * 2 + 1];
            float gi = EBIH[tid] + x0 * EWIH[tid * 2] + x1 * EWIH[tid * 2 + 1];
            ull g0 = 0ULL, g1 = 0ULL;
            const float4* wr = (const float4*)(ewhh + tid * 32);
            const ulonglong2* hp = (const ulonglong2*)H;
            #pragma unroll
            for (int k = 0; k < 8; ++k) {
                float4 wf = wr[k];
                ulonglong2 wv = *(const ulonglong2*)&wf;
                ulonglong2 hv = hp[k];
                ffma2(g0, hv.x, wv.x);
                ffma2(g1, hv.y, wv.y);
            }
            GI[tid] = gi;
            GH[tid] = EBHH[tid] + hsum2(g0) + hsum2(g1);
        }
        __syncthreads();
        if (tid < 32) {
            float r  = fsig_(GI[tid] + GH[tid]);
            float zg = fsig_(GI[32 + tid] + GH[32 + tid]);
            float n  = ftanh_(GI[64 + tid] + r * GH[64 + tid]);
            H[tid] = (1.f - zg) * n + zg * H[tid];
        }
        __syncthreads();
    }

    // ---- decoder: 30 autoregressive steps ----
    float logdet = 0.f;   // live in tid 0,1
    for (int t = 0; t < T_FUT; ++t) {
        // Phase A: GH matvec (tid<96) || lidar patch (96..167) || coords (224)
        if (tid < 96) {
            ull g0 = 0ULL, g1 = 0ULL;
            const ulonglong2* hr = (const ulonglong2*)(DWHH + tid * 36);
            const ulonglong2* hp = (const ulonglong2*)H;
            #pragma unroll
            for (int k = 0; k < 8; ++k) {
                ulonglong2 wv = hr[k];
                ulonglong2 hv = hp[k];
                ffma2(g0, hv.x, wv.x);
                ffma2(g1, hv.y, wv.y);
            }
            GH[tid] = DBHH[tid] + hsum2(g0) + hsum2(g1);
        } else {
            float q0c = Y[0], q1c = Y[1];
            float f0 = fminf(fmaxf(floorf(q0c), 0.f), 98.f);
            float f1 = fminf(fmaxf(floorf(q1c), 0.f), 98.f);
            int fy = (int)f0, fx = (int)f1;
            if (tid < 168) {
                int e = tid - 96;                 // one element each
                int rr = e / 12, cc = (e % 12) >> 1, ci = e & 1;
                int gy = fy + rr, gx = fx + cc;
                float v = 0.f;
                if (gy < 100 && gx < 100)
                    v = lidar[((b * 100 + gy) * 100 + gx) * 2 + ci];
                LID[e] = v;
            } else if (tid == 224) {
                Q4[0] = f0; Q4[1] = f1;
                Q4[2] = fminf(fmaxf(q0c - f0, 0.f), 1.f);   // ay
                Q4[3] = fminf(fmaxf(q1c - f1, 0.f), 1.f);   // ax
            }
        }
        __syncthreads();

        const int fy = (int)Q4[0], fx = (int)Q4[1];

        // Phase B: layer0 — 800 outputs over 256 threads
        for (int idx = tid; idx < 800; idx += NT) {
            int co = idx & 31, cell = idx >> 5;
            int r = cell / 5, c = cell % 5;
            ull acc = 0ULL;
            #pragma unroll
            for (int kk = 0; kk < 4; ++kk) {
                int kh = kk >> 1, kw = kk & 1;
                ull lv = *(const ull*)(LID + ((r + kh) * 6 + (c + kw)) * 2);
                ull wv = *(const ull*)(WT0 + (kk * 32 + co) * 2);
                ffma2(acc, lv, wv);
            }
            float o = fmaxf(hsum2(acc) + CB[co], 0.f);
            if (fy + r > 99 || fx + c > 99) o = 0.f;
            A0[cell * 32 + co] = o;
        }
        __syncthreads();

        // Phase C: layer1 (5->4), 4 warps x 4 cells
        if (wid < 4)
            conv_tile<4, 5, 4>(A0, A1, WT1, CB + 32, wid * 4, fy, fx, lane);
        __syncthreads();

        // Phase D: layer2 (4->3), 3 warps x 3 cells
        if (wid < 3)
            conv_tile<3, 4, 3>(A1, A2, WT2, CB + 64, wid * 3, fy, fx, lane);
        __syncthreads();

        // Phase E: layer3 (3->2), warp 0 all 4 cells + fused bilinear
        if (wid == 0) {
            float ay = Q4[2], ax = Q4[3];
            ull acc[4][2];
            #pragma unroll
            for (int c = 0; c < 4; ++c) { acc[c][0] = 0ULL; acc[c][1] = 0ULL; }
            #pragma unroll
            for (int kk = 0; kk < 4; ++kk) {
                const int kh = kk >> 1, kw = kk & 1;
                const ulonglong2* wp = (const ulonglong2*)(WT3 + (kk * 32 + lane) * 36);
                #pragma unroll
                for (int q = 0; q < 8; ++q) {
                    ulonglong2 wv = wp[q];
                    #pragma unroll
                    for (int c = 0; c < 4; ++c) {
                        int r = c >> 1, x = c & 1;
                        const ulonglong2* ap =
                            (const ulonglong2*)(A2 + ((r + kh) * 3 + (x + kw)) * 32);
                        ulonglong2 av = ap[q];
                        ffma2(acc[c][0], av.x, wv.x);
                        ffma2(acc[c][1], av.y, wv.y);
                    }
                }
            }
            const float bl = CB[96 + lane];
            float o[4];
            #pragma unroll
            for (int c = 0; c < 4; ++c) {
                int r = c >> 1, x = c & 1;
                float v = hsum2(acc[c][0]) + hsum2(acc[c][1]) + bl;
                v = fmaxf(v, 0.f);
                if (fy + r > 99 || fx + x > 99) v = 0.f;
                o[c] = v;
            }
            float top = o[0] + ax * (o[1] - o[0]);
            float bot = o[2] + ax * (o[3] - o[2]);
            X[2 + lane] = top + ay * (bot - top);
            if (lane < 2) X[lane] = Y[lane];
        }
        __syncthreads();

        // Phase F: GI matvec (96 threads)
        if (tid < 96) {
            ull a0 = 0ULL, a1 = 0ULL;
            const ulonglong2* wr = (const ulonglong2*)(DWIH + tid * 36);
            const ulonglong2* xp = (const ulonglong2*)X;
            #pragma unroll
            for (int k = 0; k < 8; ++k) {
                ulonglong2 wv = wr[k];
                ulonglong2 xv = xp[k];
                ffma2(a0, xv.x, wv.x);
                ffma2(a1, xv.y, wv.y);
            }
            ull wl = *(const ull*)(DWIH + tid * 36 + 32);
            ull xl = *(const ull*)(X + 32);
            ffma2(a0, xl, wl);
            GI[tid] = DBIH[tid] + hsum2(a0) + hsum2(a1);
        }
        __syncthreads();

        // Phase G: hidden update (32 lanes) + warp-parallel head + y-update
        if (tid < 32) {
            float r  = fsig_(GI[tid] + GH[tid]);
            float zg = fsig_(GI[32 + tid] + GH[32 + tid]);
            float n  = ftanh_(GI[64 + tid] + r * GH[64 + tid]);
            H[tid] = (1.f - zg) * n + zg * H[tid];
            __syncwarp();
            // head: 4 outputs x 32 features over 32 lanes (8 lanes per output)
            int o = tid >> 3, k0 = (tid & 7) * 4;
            const float* wr = WC + o * 32 + k0;
            const float* hr = H + k0;
            float part = wr[0] * hr[0];
            part = fmaf(wr[1], hr[1], part);
            part = fmaf(wr[2], hr[2], part);
            part = fmaf(wr[3], hr[3], part);
            #pragma unroll
            for (int off = 4; off; off >>= 1)
                part += __shfl_xor_sync(0xffffffffu, part, off);
            float v = part + BC[o];
            float locv = __shfl_sync(0xffffffffu, v, (tid & 1) * 8);
            float spv  = __shfl_sync(0xffffffffu, v, 16 + (tid & 1) * 8);
            if (tid < 2) {
                float s  = fsoftplus_(spv);
                float zt = z[(b * T_FUT + t) * 2 + tid];
                float yn = 2.f * Y[tid] - Y[2 + tid] + locv + s * zt;
                out[(b * T_FUT + t) * 2 + tid] = yn;
                logdet += flogf_(s);
                Y[2 + tid] = Y[tid];
                Y[tid] = yn;
            }
        }
        __syncthreads();   // Y/H visible for next step
    }

    if (tid < 2) LD[tid] = logdet;
    __syncthreads();
    if (tid == 0) out[B_N * T_FUT * 2 + b] = LD[0] + LD[1];
}

extern "C" void kernel_launch(void* const* d_in, const int* in_sizes, int n_in,
                              void* d_out, int out_size)
{
    const float* z    = (const float*)d_in[0];
    const float* pp   = (const float*)d_in[1];
    const float* lid  = (const float*)d_in[2];
    const float* c0w  = (const float*)d_in[3];
    const float* c0b  = (const float*)d_in[4];
    const float* c1w  = (const float*)d_in[5];
    const float* c1b  = (const float*)d_in[6];
    const float* c2w  = (const float*)d_in[7];
    const float* c2b  = (const float*)d_in[8];
    const float* c3w  = (const float*)d_in[9];
    const float* c3b  = (const float*)d_in[10];
    const float* ewih = (const float*)d_in[11];
    const float* ewhh = (const float*)d_in[12];
    const float* ebih = (const float*)d_in[13];
    const float* ebhh = (const float*)d_in[14];
    const float* dwih = (const float*)d_in[15];
    const float* dwhh = (const float*)d_in[16];
    const float* dbih = (const float*)d_in[17];
    const float* dbhh = (const float*)d_in[18];
    const float* w1   = (const float*)d_in[19];
    const float* b1   = (const float*)d_in[20];
    const float* w2   = (const float*)d_in[21];
    const float* b2   = (const float*)d_in[22];
    float* out = (float*)d_out;

    cudaFuncSetAttribute(r2p2_kernel,
                         cudaFuncAttributeMaxDynamicSharedMemorySize, SMEM_BYTES);

    r2p2_kernel<<<B_N, NT, SMEM_BYTES>>>(z, pp, lid,
        c0w, c0b, c1w, c1b, c2w, c2b, c3w, c3b,
        ewih, ewhh, ebih, ebhh, dwih, dwhh, dbih, dbhh,
        w1, b1, w2, b2, out);
}

// round 7
// speedup vs baseline: 1.8258x; 1.2296x over previous
#include <cuda_runtime.h>
#include <math.h>

#define B_N    256
#define T_PAST 20
#define T_FUT  30
#define NT     256

// ---- shared memory layout (float indices) ----
#define SM_WT1   0        // 4*32*36 = 4608  conv1 [kk][co][ci] stride 36
#define SM_WT2   4608
#define SM_WT3   9216
#define SM_WT0   13824    // 4*32*2
#define SM_CB    14080    // 128
#define SM_DWIH  14208    // 96*36
#define SM_DWHH  17664    // 96*36
#define SM_WC    21120    // 128
#define SM_BC    21248    // 4
#define SM_A0    21252    // 800
#define SM_A1    22052    // 512
#define SM_A2    22564    // 288
#define SM_LID   22980    // 72
#define SM_X     23052    // 36
#define SM_H     23088    // 32
#define SM_GI    23120    // 96
#define SM_GH    23216    // 96
#define SM_Y     23312    // 4
#define SM_LD    23316    // 2
#define SM_Q4    23320    // 4: f0,f1,ay,ax
#define SM_EWIH  23324    // 96*2
#define SM_EBIH  23516    // 96
#define SM_EBHH  23612    // 96
#define SM_DBIH  23708    // 96
#define SM_DBHH  23804    // 96
#define SM_TOTAL 23900
#define SMEM_BYTES (SM_TOTAL * 4)

typedef unsigned long long ull;

__device__ __forceinline__ void ffma2(ull& d, ull a, ull b) {
    asm("fma.rn.f32x2 %0, %1, %2, %0;" : "+l"(d) : "l"(a), "l"(b));
}
__device__ __forceinline__ float hsum2(ull v) {
    float lo, hi;
    asm("mov.b64 {%0,%1}, %2;" : "=f"(lo), "=f"(hi) : "l"(v));
    return lo + hi;
}
// ---- fast transcendentals (MUFU) ----
__device__ __forceinline__ float fexp2_(float x) {
    float r; asm("ex2.approx.f32 %0, %1;" : "=f"(r) : "f"(x)); return r;
}
__device__ __forceinline__ float flg2_(float x) {
    float r; asm("lg2.approx.f32 %0, %1;" : "=f"(r) : "f"(x)); return r;
}
__device__ __forceinline__ float frcp_(float x) {
    float r; asm("rcp.approx.f32 %0, %1;" : "=f"(r) : "f"(x)); return r;
}
__device__ __forceinline__ float ftanh_(float x) {
    float r; asm("tanh.approx.f32 %0, %1;" : "=f"(r) : "f"(x)); return r;
}
#define LOG2E 1.4426950408889634f
#define LN2   0.6931471805599453f
__device__ __forceinline__ float fsig_(float x) {
    return frcp_(1.f + fexp2_(-LOG2E * x));
}
__device__ __forceinline__ float flogf_(float x) { return flg2_(x) * LN2; }
__device__ __forceinline__ float fsoftplus_(float x) {
    return (x > 20.f) ? x : flg2_(1.f + fexp2_(LOG2E * x)) * LN2;
}

// One conv tile: CPW cells starting at cb, lane = output channel.
template <int OS, int IS, int CPW>
__device__ __forceinline__ void conv_tile(const float* __restrict__ ain,
                                          float* __restrict__ aout,
                                          const float* __restrict__ wT,
                                          const float* __restrict__ bias,
                                          int cb, int fy, int fx, int lane)
{
    int rr[CPW], xx[CPW];
    #pragma unroll
    for (int c = 0; c < CPW; ++c) { rr[c] = (cb + c) / OS; xx[c] = (cb + c) % OS; }

    ull acc[CPW][2];
    #pragma unroll
    for (int c = 0; c < CPW; ++c) { acc[c][0] = 0ULL; acc[c][1] = 0ULL; }

    #pragma unroll
    for (int kk = 0; kk < 4; ++kk) {
        const int kh = kk >> 1, kw = kk & 1;
        const ulonglong2* wp = (const ulonglong2*)(wT + (kk * 32 + lane) * 36);
        const ulonglong2* ap[CPW];
        #pragma unroll
        for (int c = 0; c < CPW; ++c)
            ap[c] = (const ulonglong2*)(ain + ((rr[c] + kh) * IS + (xx[c] + kw)) * 32);
        #pragma unroll
        for (int q = 0; q < 8; ++q) {
            ulonglong2 wv = wp[q];
            #pragma unroll
            for (int c = 0; c < CPW; ++c) {
                ulonglong2 av = ap[c][q];
                ffma2(acc[c][0], av.x, wv.x);
                ffma2(acc[c][1], av.y, wv.y);
            }
        }
    }
    const float bl = bias[lane];
    #pragma unroll
    for (int c = 0; c < CPW; ++c) {
        float o = hsum2(acc[c][0]) + hsum2(acc[c][1]) + bl;
        o = fmaxf(o, 0.f);
        if (fy + rr[c] > 99 || fx + xx[c] > 99) o = 0.f;
        aout[(cb + c) * 32 + lane] = o;
    }
}

extern __shared__ float sm[];

__global__ void __launch_bounds__(NT, 2)
r2p2_kernel(const float* __restrict__ z,
            const float* __restrict__ pp,
            const float* __restrict__ lidar,
            const float* __restrict__ c0w, const float* __restrict__ c0b,
            const float* __restrict__ c1w, const float* __restrict__ c1b,
            const float* __restrict__ c2w, const float* __restrict__ c2b,
            const float* __restrict__ c3w, const float* __restrict__ c3b,
            const float* __restrict__ ewih, const float* __restrict__ ewhh,
            const float* __restrict__ ebih, const float* __restrict__ ebhh,
            const float* __restrict__ dwih, const float* __restrict__ dwhh,
            const float* __restrict__ dbih, const float* __restrict__ dbhh,
            const float* __restrict__ w1, const float* __restrict__ b1,
            const float* __restrict__ w2, const float* __restrict__ b2,
            float* __restrict__ out)
{
    const int b = blockIdx.x;
    const int tid = threadIdx.x;
    const int wid = tid >> 5, lane = tid & 31;

    float* WT1 = sm + SM_WT1;  float* WT2 = sm + SM_WT2;  float* WT3 = sm + SM_WT3;
    float* WT0 = sm + SM_WT0;  float* CB  = sm + SM_CB;
    float* DWIH = sm + SM_DWIH; float* DWHH = sm + SM_DWHH;
    float* WC = sm + SM_WC;    float* BC = sm + SM_BC;
    float* A0 = sm + SM_A0;  float* A1 = sm + SM_A1;  float* A2 = sm + SM_A2;
    float* LID = sm + SM_LID; float* X = sm + SM_X;  float* H = sm + SM_H;
    float* GI = sm + SM_GI;   float* GH = sm + SM_GH;
    float* Y  = sm + SM_Y;    float* LD = sm + SM_LD; float* Q4 = sm + SM_Q4;
    float* EWIH = sm + SM_EWIH; float* EBIH = sm + SM_EBIH; float* EBHH = sm + SM_EBHH;
    float* DBIH = sm + SM_DBIH; float* DBHH = sm + SM_DBHH;

    // ---- setup: weight transposes + fused MLP collapse ----
    {
        const float* srcs[3] = { c1w, c2w, c3w };
        float* dsts[3] = { WT1, WT2, WT3 };
        #pragma unroll
        for (int l = 0; l < 3; ++l) {
            const float* s = srcs[l]; float* d = dsts[l];
            for (int idx = tid; idx < 4096; idx += NT) {
                int co = idx & 31, ci = (idx >> 5) & 31, kk = idx >> 10;
                d[(kk * 32 + co) * 36 + ci] = s[idx];
            }
        }
        for (int idx = tid; idx < 256; idx += NT) {
            int co = idx & 31, ci = (idx >> 5) & 1, kk = idx >> 6;
            WT0[(kk * 32 + co) * 2 + ci] = c0w[idx];
        }
    }
    if (tid < 32) {
        CB[tid] = c0b[tid]; CB[32 + tid] = c1b[tid];
        CB[64 + tid] = c2b[tid]; CB[96 + tid] = c3b[tid];
    }
    for (int idx = tid; idx < 96 * 34; idx += NT) {
        int j = idx / 34, k = idx % 34;
        DWIH[j * 36 + k] = dwih[idx];
    }
    for (int idx = tid; idx < 96 * 32; idx += NT) {
        int j = idx >> 5, k = idx & 31;
        DWHH[j * 36 + k] = dwhh[idx];
    }
    if (tid < 96) {
        EWIH[tid * 2] = ewih[tid * 2]; EWIH[tid * 2 + 1] = ewih[tid * 2 + 1];
        EBIH[tid] = ebih[tid]; EBHH[tid] = ebhh[tid];
        DBIH[tid] = dbih[tid]; DBHH[tid] = dbhh[tid];
    }
    // Wc = W2@W1 (threads 0..127), bc = W2@b1+b2 (threads 128..255)
    if (tid < 128) {
        int o = tid >> 5, i = tid & 31;
        const float* w2r = w2 + o * 512;
        float a0 = 0.f, a1 = 0.f;
        for (int k = 0; k < 512; k += 2) {
            a0 = fmaf(w2r[k + 0], w1[(k + 0) * 32 + i], a0);
            a1 = fmaf(w2r[k + 1], w1[(k + 1) * 32 + i], a1);
        }
        WC[tid] = a0 + a1;
    } else {
        int o = (tid - 128) >> 5, l = tid & 31;
        float acc = 0.f;
        for (int k = l; k < 512; k += 32) acc = fmaf(w2[o * 512 + k], b1[k], acc);
        #pragma unroll
        for (int off = 16; off; off >>= 1)
            acc += __shfl_xor_sync(0xffffffffu, acc, off);
        if (l == 0) BC[o] = acc + b2[o];
    }
    if (tid < 32) H[tid] = 0.f;
    if (tid < 2) {
        Y[tid]     = pp[(b * T_PAST + 19) * 2 + tid];   // y_{t-1}
        Y[2 + tid] = pp[(b * T_PAST + 18) * 2 + tid];   // y_{t-2}
    }
    __syncthreads();

    // ---- encoder GRU: 20 steps ----
    for (int t = 0; t < T_PAST; ++t) {
        if (tid < 96) {
            float x0 = pp[(b * T_PAST + t) * 2];
            float x1 = pp[(b * T_PAST + t) * 2 + 1];
            float gi = EBIH[tid] + x0 * EWIH[tid * 2] + x1 * EWIH[tid * 2 + 1];
            ull g0 = 0ULL, g1 = 0ULL;
            const float4* wr = (const float4*)(ewhh + tid * 32);
            const ulonglong2* hp = (const ulonglong2*)H;
            #pragma unroll
            for (int k = 0; k < 8; ++k) {
                float4 wf = wr[k];
                ulonglong2 wv = *(const ulonglong2*)&wf;
                ulonglong2 hv = hp[k];
                ffma2(g0, hv.x, wv.x);
                ffma2(g1, hv.y, wv.y);
            }
            GI[tid] = gi;
            GH[tid] = EBHH[tid] + hsum2(g0) + hsum2(g1);
        }
        __syncthreads();
        if (tid < 32) {
            float r  = fsig_(GI[tid] + GH[tid]);
            float zg = fsig_(GI[32 + tid] + GH[32 + tid]);
            float n  = ftanh_(GI[64 + tid] + r * GH[64 + tid]);
            H[tid] = (1.f - zg) * n + zg * H[tid];
        }
        __syncthreads();
    }

    // ---- decoder: 30 autoregressive steps ----
    float logdet = 0.f;   // live in tid 0,1
    for (int t = 0; t < T_FUT; ++t) {
        // Phase A: GH matvec (tid<96) || lidar patch (96..167) || coords (224)
        if (tid < 96) {
            ull g0 = 0ULL, g1 = 0ULL;
            const ulonglong2* hr = (const ulonglong2*)(DWHH + tid * 36);
            const ulonglong2* hp = (const ulonglong2*)H;
            #pragma unroll
            for (int k = 0; k < 8; ++k) {
                ulonglong2 wv = hr[k];
                ulonglong2 hv = hp[k];
                ffma2(g0, hv.x, wv.x);
                ffma2(g1, hv.y, wv.y);
            }
            GH[tid] = DBHH[tid] + hsum2(g0) + hsum2(g1);
        } else {
            float q0c = Y[0], q1c = Y[1];
            float f0 = fminf(fmaxf(floorf(q0c), 0.f), 98.f);
            float f1 = fminf(fmaxf(floorf(q1c), 0.f), 98.f);
            int fy = (int)f0, fx = (int)f1;
            if (tid < 168) {
                int e = tid - 96;                 // one element each
                int rr = e / 12, cc = (e % 12) >> 1, ci = e & 1;
                int gy = fy + rr, gx = fx + cc;
                float v = 0.f;
                if (gy < 100 && gx < 100)
                    v = lidar[((b * 100 + gy) * 100 + gx) * 2 + ci];
                LID[e] = v;
            } else if (tid == 224) {
                Q4[0] = f0; Q4[1] = f1;
                Q4[2] = fminf(fmaxf(q0c - f0, 0.f), 1.f);   // ay
                Q4[3] = fminf(fmaxf(q1c - f1, 0.f), 1.f);   // ax
            }
        }
        __syncthreads();

        const int fy = (int)Q4[0], fx = (int)Q4[1];

        // Phase B: layer0 — 800 outputs over 256 threads
        for (int idx = tid; idx < 800; idx += NT) {
            int co = idx & 31, cell = idx >> 5;
            int r = cell / 5, c = cell % 5;
            ull acc = 0ULL;
            #pragma unroll
            for (int kk = 0; kk < 4; ++kk) {
                int kh = kk >> 1, kw = kk & 1;
                ull lv = *(const ull*)(LID + ((r + kh) * 6 + (c + kw)) * 2);
                ull wv = *(const ull*)(WT0 + (kk * 32 + co) * 2);
                ffma2(acc, lv, wv);
            }
            float o = fmaxf(hsum2(acc) + CB[co], 0.f);
            if (fy + r > 99 || fx + c > 99) o = 0.f;
            A0[cell * 32 + co] = o;
        }
        __syncthreads();

        // Phase C: layer1 (5->4), 4 warps x 4 cells
        if (wid < 4)
            conv_tile<4, 5, 4>(A0, A1, WT1, CB + 32, wid * 4, fy, fx, lane);
        __syncthreads();

        // Phase D: layer2 (4->3), 3 warps x 3 cells
        if (wid < 3)
            conv_tile<3, 4, 3>(A1, A2, WT2, CB + 64, wid * 3, fy, fx, lane);
        __syncthreads();

        // Phase E: layer3 (3->2), warp 0 all 4 cells + fused bilinear
        if (wid == 0) {
            float ay = Q4[2], ax = Q4[3];
            ull acc[4][2];
            #pragma unroll
            for (int c = 0; c < 4; ++c) { acc[c][0] = 0ULL; acc[c][1] = 0ULL; }
            #pragma unroll
            for (int kk = 0; kk < 4; ++kk) {
                const int kh = kk >> 1, kw = kk & 1;
                const ulonglong2* wp = (const ulonglong2*)(WT3 + (kk * 32 + lane) * 36);
                #pragma unroll
                for (int q = 0; q < 8; ++q) {
                    ulonglong2 wv = wp[q];
                    #pragma unroll
                    for (int c = 0; c < 4; ++c) {
                        int r = c >> 1, x = c & 1;
                        const ulonglong2* ap =
                            (const ulonglong2*)(A2 + ((r + kh) * 3 + (x + kw)) * 32);
                        ulonglong2 av = ap[q];
                        ffma2(acc[c][0], av.x, wv.x);
                        ffma2(acc[c][1], av.y, wv.y);
                    }
                }
            }
            const float bl = CB[96 + lane];
            float o[4];
            #pragma unroll
            for (int c = 0; c < 4; ++c) {
                int r = c >> 1, x = c & 1;
                float v = hsum2(acc[c][0]) + hsum2(acc[c][1]) + bl;
                v = fmaxf(v, 0.f);
                if (fy + r > 99 || fx + x > 99) v = 0.f;
                o[c] = v;
            }
            float top = o[0] + ax * (o[1] - o[0]);
            float bot = o[2] + ax * (o[3] - o[2]);
            X[2 + lane] = top + ay * (bot - top);
            if (lane < 2) X[lane] = Y[lane];
        }
        __syncthreads();

        // Phase F: GI matvec (96 threads)
        if (tid < 96) {
            ull a0 = 0ULL, a1 = 0ULL;
            const ulonglong2* wr = (const ulonglong2*)(DWIH + tid * 36);
            const ulonglong2* xp = (const ulonglong2*)X;
            #pragma unroll
            for (int k = 0; k < 8; ++k) {
                ulonglong2 wv = wr[k];
                ulonglong2 xv = xp[k];
                ffma2(a0, xv.x, wv.x);
                ffma2(a1, xv.y, wv.y);
            }
            ull wl = *(const ull*)(DWIH + tid * 36 + 32);
            ull xl = *(const ull*)(X + 32);
            ffma2(a0, xl, wl);
            GI[tid] = DBIH[tid] + hsum2(a0) + hsum2(a1);
        }
        __syncthreads();

        // Phase G: hidden update (32 lanes) + warp-parallel head + y-update
        if (tid < 32) {
            float r  = fsig_(GI[tid] + GH[tid]);
            float zg = fsig_(GI[32 + tid] + GH[32 + tid]);
            float n  = ftanh_(GI[64 + tid] + r * GH[64 + tid]);
            H[tid] = (1.f - zg) * n + zg * H[tid];
            __syncwarp();
            // head: 4 outputs x 32 features over 32 lanes (8 lanes per output)
            int o = tid >> 3, k0 = (tid & 7) * 4;
            const float* wr = WC + o * 32 + k0;
            const float* hr = H + k0;
            float part = wr[0] * hr[0];
            part = fmaf(wr[1], hr[1], part);
            part = fmaf(wr[2], hr[2], part);
            part = fmaf(wr[3], hr[3], part);
            #pragma unroll
            for (int off = 4; off; off >>= 1)
                part += __shfl_xor_sync(0xffffffffu, part, off);
            float v = part + BC[o];
            float locv = __shfl_sync(0xffffffffu, v, (tid & 1) * 8);
            float spv  = __shfl_sync(0xffffffffu, v, 16 + (tid & 1) * 8);
            if (tid < 2) {
                float s  = fsoftplus_(spv);
                float zt = z[(b * T_FUT + t) * 2 + tid];
                float yn = 2.f * Y[tid] - Y[2 + tid] + locv + s * zt;
                out[(b * T_FUT + t) * 2 + tid] = yn;
                logdet += flogf_(s);
                Y[2 + tid] = Y[tid];
                Y[tid] = yn;
            }
        }
        __syncthreads();   // Y/H visible for next step
    }

    if (tid < 2) LD[tid] = logdet;
    __syncthreads();
    if (tid == 0) out[B_N * T_FUT * 2 + b] = LD[0] + LD[1];
}

extern "C" void kernel_launch(void* const* d_in, const int* in_sizes, int n_in,
                              void* d_out, int out_size)
{
    const float* z    = (const float*)d_in[0];
    const float* pp   = (const float*)d_in[1];
    const float* lid  = (const float*)d_in[2];
    const float* c0w  = (const float*)d_in[3];
    const float* c0b  = (const float*)d_in[4];
    const float* c1w  = (const float*)d_in[5];
    const float* c1b  = (const float*)d_in[6];
    const float* c2w  = (const float*)d_in[7];
    const float* c2b  = (const float*)d_in[8];
    const float* c3w  = (const float*)d_in[9];
    const float* c3b  = (const float*)d_in[10];
    const float* ewih = (const float*)d_in[11];
    const float* ewhh = (const float*)d_in[12];
    const float* ebih = (const float*)d_in[13];
    const float* ebhh = (const float*)d_in[14];
    const float* dwih = (const float*)d_in[15];
    const float* dwhh = (const float*)d_in[16];
    const float* dbih = (const float*)d_in[17];
    const float* dbhh = (const float*)d_in[18];
    const float* w1   = (const float*)d_in[19];
    const float* b1   = (const float*)d_in[20];
    const float* w2   = (const float*)d_in[21];
    const float* b2   = (const float*)d_in[22];
    float* out = (float*)d_out;

    cudaFuncSetAttribute(r2p2_kernel,
                         cudaFuncAttributeMaxDynamicSharedMemorySize, SMEM_BYTES);

    r2p2_kernel<<<B_N, NT, SMEM_BYTES>>>(z, pp, lid,
        c0w, c0b, c1w, c1b, c2w, c2b, c3w, c3b,
        ewih, ewhh, ebih, ebhh, dwih, dwhh, dbih, dbhh,
        w1, b1, w2, b2, out);
}